// round 5
// baseline (speedup 1.0000x reference)
#include <cuda_runtime.h>
#include <cuda_bf16.h>
#include <cstdint>

// ---------------- problem constants ----------------
#define NMAX    8192
#define DDIM    128
#define TM      128
#define NTILES  (NMAX / TM)           // 64
#define CC      14.426950408889634f   // log2(e) / TEMPERATURE(=0.1)
#define INVCC   0.069314718055994531f // 1/CC
#define LN2F    0.69314718055994531f
#define SKIP_T  25.0f

#define TILE_BYTES (TM * DDIM * 2)    // 32 KB bf16

// smem layout (bytes)
#define OFF_A      0
#define OFF_B      (TILE_BYTES)                 // 32768
#define OFF_SROW   (2 * TILE_BYTES)             // 128 f32
#define OFF_SCOL   (OFF_SROW + 512)             // 128 f32
#define OFF_ROWMM  (OFF_SCOL + 512)             // 2 x 128 float2 (max,min)
#define OFF_ROWS   (OFF_ROWMM + 2048)           // 2 x 128 f32
#define OFF_COLMM  (OFF_ROWS + 1024)            // 4 x 128 float2
#define OFF_THR    (OFF_COLMM + 4096)           // 128 float2 (hi,lo)
#define OFF_MCOL   (OFF_THR + 1024)             // 128 f32
#define OFF_COLS   (OFF_MCOL + 512)             // 4 x 128 f32
#define SMEM_K2    (OFF_COLS + 2048)            // ~77.3 KB

__device__ __align__(16) __nv_bfloat16 g_tbf[NMAX * DDIM];
__device__ float  g_sC[NMAX];                    // s_i * CC
__device__ float  g_dlabE[NMAX];                 // |s_i - u_i| * CC
__device__ __align__(16) float2 g_c[NMAX * NTILES];  // [row][slot] = (max, sum)
__device__ float  g_bpart[128];

// ---------------- low-level helpers ----------------
__device__ __forceinline__ float ex2f(float x) {
    float r;
    asm("ex2.approx.f32 %0, %1;" : "=f"(r) : "f"(x));
    return r;
}
__device__ __forceinline__ float lg2f(float x) {
    float r;
    asm("lg2.approx.f32 %0, %1;" : "=f"(r) : "f"(x));
    return r;
}
__device__ __forceinline__ uint32_t smem_u32(const void* p) {
    uint32_t a;
    asm("{ .reg .u64 t; cvta.to.shared.u64 t, %1; cvt.u32.u64 %0, t; }" : "=r"(a) : "l"(p));
    return a;
}
__device__ __forceinline__ void cp_async16(uint32_t dst, const void* src) {
    asm volatile("cp.async.cg.shared.global [%0], [%1], 16;" :: "r"(dst), "l"(src) : "memory");
}
#define CP_COMMIT() asm volatile("cp.async.commit_group;" ::: "memory")
#define CP_WAIT0()  asm volatile("cp.async.wait_group 0;" ::: "memory")

#define LDSM_X4(r, addr)                                                      \
    asm volatile("ldmatrix.sync.aligned.m8n8.x4.shared.b16 {%0,%1,%2,%3}, [%4];" \
        : "=r"((r)[0]), "=r"((r)[1]), "=r"((r)[2]), "=r"((r)[3]) : "r"(addr))

__device__ __forceinline__ void mma16816(float* c, const uint32_t* a,
                                         uint32_t b0, uint32_t b1) {
    asm volatile(
        "mma.sync.aligned.m16n8k16.row.col.f32.bf16.bf16.f32 "
        "{%0,%1,%2,%3}, {%4,%5,%6,%7}, {%8,%9}, {%0,%1,%2,%3};"
        : "+f"(c[0]), "+f"(c[1]), "+f"(c[2]), "+f"(c[3])
        : "r"(a[0]), "r"(a[1]), "r"(a[2]), "r"(a[3]), "r"(b0), "r"(b1));
}
__device__ __forceinline__ uint32_t swz(int r, int c) {
    return (uint32_t)(r * 256 + ((c ^ (r & 7)) << 4));
}

// ---------------- K1: per-row scalars + t -> bf16 (fused) ----------------
__global__ void k1_rowprep(const float* __restrict__ q, const float* __restrict__ t,
                           const int* __restrict__ label, const int* __restrict__ jidx,
                           int n) {
    int i = blockIdx.x * 8 + (threadIdx.x >> 5);
    if (i >= n) return;
    int lane = threadIdx.x & 31;
    int j = jidx[i];

    float4 a = reinterpret_cast<const float4*>(q + (size_t)i * DDIM)[lane];
    float4 b = reinterpret_cast<const float4*>(q + (size_t)j * DDIM)[lane];
    float s = a.x * b.x + a.y * b.y + a.z * b.z + a.w * b.w;
    #pragma unroll
    for (int o = 16; o; o >>= 1) s += __shfl_xor_sync(0xFFFFFFFFu, s, o);

    int l = label[i];
    int col;
    if (l == i)       col = j;
    else if (j > i)   col = (l > i && l <= j) ? l - 1 : l;
    else              col = (l >= j && l < i) ? l + 1 : l;

    float4 c = reinterpret_cast<const float4*>(t + (size_t)i   * DDIM)[lane];
    float4 d = reinterpret_cast<const float4*>(t + (size_t)col * DDIM)[lane];
    float u = c.x * d.x + c.y * d.y + c.z * d.z + c.w * d.w;
    #pragma unroll
    for (int o = 16; o; o >>= 1) u += __shfl_xor_sync(0xFFFFFFFFu, u, o);

    // fused bf16 conversion of row i (registers already hold t[i])
    __nv_bfloat162 p0, p1;
    p0.x = __float2bfloat16(c.x); p0.y = __float2bfloat16(c.y);
    p1.x = __float2bfloat16(c.z); p1.y = __float2bfloat16(c.w);
    uint2 pk;
    pk.x = *reinterpret_cast<uint32_t*>(&p0);
    pk.y = *reinterpret_cast<uint32_t*>(&p1);
    reinterpret_cast<uint2*>(g_tbf + (size_t)i * DDIM)[lane] = pk;

    if (lane == 0) {
        g_sC[i]    = s * CC;
        g_dlabE[i] = fabsf(s - u) * CC;
    }
}

// ---------------- K2: symmetric tiles + dual-direction LSE partials ----------
__global__ void __launch_bounds__(256, 2) k2_sym(int ntiles) {
    extern __shared__ char smem[];
    const int tid = threadIdx.x, wid = tid >> 5, lane = tid & 31;
    const int wr = wid & 3;
    const int wc = wid >> 2;
    const int g = lane >> 2, tig = lane & 3;

    // decode blockIdx -> (I, J), I <= J
    int b = blockIdx.x;
    int I;
    {
        float nn = 2.0f * ntiles + 1.0f;
        I = (int)((nn - sqrtf(nn * nn - 8.0f * (float)b)) * 0.5f);
        if (I < 0) I = 0;
        while ((I + 1) * ntiles - ((I + 1) * I) / 2 <= b) ++I;
        while (I * ntiles - (I * (I - 1)) / 2 > b) --I;
    }
    const int J = I + (b - (I * ntiles - (I * (I - 1)) / 2));
    const bool diag = (I == J);
    const int row0 = I * TM, col0 = J * TM;

    const uint32_t sA = smem_u32(smem);
    const uint32_t sB = diag ? sA : (sA + OFF_B);
    float*  sRowBuf = reinterpret_cast<float*>(smem + OFF_SROW);
    float*  sColBuf = reinterpret_cast<float*>(smem + OFF_SCOL);
    float2* rowMM   = reinterpret_cast<float2*>(smem + OFF_ROWMM);
    float*  rowSbuf = reinterpret_cast<float*>(smem + OFF_ROWS);
    float2* colMM   = reinterpret_cast<float2*>(smem + OFF_COLMM);
    float2* gThr    = reinterpret_cast<float2*>(smem + OFF_THR);
    float*  gMcol   = reinterpret_cast<float*>(smem + OFF_MCOL);
    float*  colSbuf = reinterpret_cast<float*>(smem + OFF_COLS);

    // ---- stage tiles + s vectors ----
    {
        const char* Ag = (const char*)(g_tbf + (size_t)row0 * DDIM);
        for (int idx = tid; idx < 2048; idx += 256)
            cp_async16(sA + swz(idx >> 4, idx & 15), Ag + idx * 16);
        if (!diag) {
            const char* Bg = (const char*)(g_tbf + (size_t)col0 * DDIM);
            for (int idx = tid; idx < 2048; idx += 256)
                cp_async16(sA + OFF_B + swz(idx >> 4, idx & 15), Bg + idx * 16);
        }
        if (tid < 128) sRowBuf[tid] = g_sC[row0 + tid];
        else           sColBuf[tid - 128] = g_sC[col0 + tid - 128];
        CP_COMMIT();
        CP_WAIT0();
        __syncthreads();
    }

    // ---- 128x128x128 MMA: warp does 32x64 ----
    float acc[2][8][4];
    #pragma unroll
    for (int mf = 0; mf < 2; mf++)
        #pragma unroll
        for (int nf = 0; nf < 8; nf++)
            #pragma unroll
            for (int e = 0; e < 4; e++) acc[mf][nf][e] = 0.f;

    #pragma unroll
    for (int kc = 0; kc < 8; kc++) {
        uint32_t a0[4], a1[4];
        {
            int r = wr * 32 + (lane & 15);
            int c = kc * 2 + (lane >> 4);
            LDSM_X4(a0, sA + swz(r, c));
            LDSM_X4(a1, sA + swz(r + 16, c));
        }
        #pragma unroll
        for (int p = 0; p < 4; p++) {
            uint32_t bb[4];
            int r = wc * 64 + p * 16 + ((lane >> 4) << 3) + (lane & 7);
            int c = kc * 2 + ((lane >> 3) & 1);
            LDSM_X4(bb, sB + swz(r, c));
            mma16816(acc[0][2 * p],     a0, bb[0], bb[1]);
            mma16816(acc[0][2 * p + 1], a0, bb[2], bb[3]);
            mma16816(acc[1][2 * p],     a1, bb[0], bb[1]);
            mma16816(acc[1][2 * p + 1], a1, bb[2], bb[3]);
        }
    }
    // frag coords: row_local = wr*32 + mf*16 + (e>>1)*8 + g
    //              col_local = wc*64 + nf*8 + tig*2 + (e&1)

    // ======== pass 1: raw max/min per row and per column ========
    float rmax[4], rmin[4], cmax[16], cmin[16];
    #pragma unroll
    for (int qq = 0; qq < 4; qq++) { rmax[qq] = -1e30f; rmin[qq] = 1e30f; }
    #pragma unroll
    for (int ii = 0; ii < 16; ii++) { cmax[ii] = -1e30f; cmin[ii] = 1e30f; }
    #pragma unroll
    for (int mf = 0; mf < 2; mf++)
        #pragma unroll
        for (int nf = 0; nf < 8; nf++)
            #pragma unroll
            for (int e = 0; e < 4; e++) {
                float a = acc[mf][nf][e];
                int qq = mf * 2 + (e >> 1), ii = nf * 2 + (e & 1);
                rmax[qq] = fmaxf(rmax[qq], a);
                rmin[qq] = fminf(rmin[qq], a);
                cmax[ii] = fmaxf(cmax[ii], a);
                cmin[ii] = fminf(cmin[ii], a);
            }

    // ---- row merge across tig, then across wc ----
    #pragma unroll
    for (int qq = 0; qq < 4; qq++) {
        rmax[qq] = fmaxf(rmax[qq], __shfl_xor_sync(0xFFFFFFFFu, rmax[qq], 1));
        rmax[qq] = fmaxf(rmax[qq], __shfl_xor_sync(0xFFFFFFFFu, rmax[qq], 2));
        rmin[qq] = fminf(rmin[qq], __shfl_xor_sync(0xFFFFFFFFu, rmin[qq], 1));
        rmin[qq] = fminf(rmin[qq], __shfl_xor_sync(0xFFFFFFFFu, rmin[qq], 2));
    }
    if (tig == 0) {
        #pragma unroll
        for (int qq = 0; qq < 4; qq++) {
            int rl = wr * 32 + (qq >> 1) * 16 + (qq & 1) * 8 + g;
            rowMM[wc * 128 + rl] = make_float2(rmax[qq], rmin[qq]);
        }
    }
    __syncthreads();

    // ---- col merge across g (shfl 4,8,16), stage per warp-row ----
    #pragma unroll
    for (int ii = 0; ii < 16; ii++) {
        cmax[ii] = fmaxf(cmax[ii], __shfl_xor_sync(0xFFFFFFFFu, cmax[ii], 4));
        cmax[ii] = fmaxf(cmax[ii], __shfl_xor_sync(0xFFFFFFFFu, cmax[ii], 8));
        cmax[ii] = fmaxf(cmax[ii], __shfl_xor_sync(0xFFFFFFFFu, cmax[ii], 16));
        cmin[ii] = fminf(cmin[ii], __shfl_xor_sync(0xFFFFFFFFu, cmin[ii], 4));
        cmin[ii] = fminf(cmin[ii], __shfl_xor_sync(0xFFFFFFFFu, cmin[ii], 8));
        cmin[ii] = fminf(cmin[ii], __shfl_xor_sync(0xFFFFFFFFu, cmin[ii], 16));
    }
    if (!diag && lane < 4) {
        #pragma unroll
        for (int ii = 0; ii < 16; ii++) {
            int cl = wc * 64 + (ii >> 1) * 8 + lane * 2 + (ii & 1);
            colMM[wr * 128 + cl] = make_float2(cmax[ii], cmin[ii]);
        }
    }
    __syncthreads();

    // ---- per-column thresholds (wid 0 & 4 compute 64 cols each) ----
    if (!diag && wr == 0) {
        #pragma unroll
        for (int rep = 0; rep < 2; rep++) {
            int cl = wc * 64 + lane + rep * 32;
            float2 v0 = colMM[cl], v1 = colMM[128 + cl];
            float2 v2 = colMM[256 + cl], v3 = colMM[384 + cl];
            float m = fmaxf(fmaxf(v0.x, v1.x), fmaxf(v2.x, v3.x));
            float mn = fminf(fminf(v0.y, v1.y), fminf(v2.y, v3.y));
            float sc = sColBuf[cl];
            float Mc = fmaxf(fmaf(m, CC, -sc), fmaf(mn, -CC, sc));
            gMcol[cl] = Mc;
            gThr[cl] = make_float2((sc + (Mc - SKIP_T)) * INVCC,
                                   (sc - (Mc - SKIP_T)) * INVCC);
        }
    }
    __syncthreads();

    // ---- row thresholds (regs) ----
    float Mrow[4], rhi[4], rlo[4], Srow[4];
    #pragma unroll
    for (int qq = 0; qq < 4; qq++) {
        int rl = wr * 32 + (qq >> 1) * 16 + (qq & 1) * 8 + g;
        float2 o = rowMM[(1 - wc) * 128 + rl];
        float amax = fmaxf(rmax[qq], o.x);
        float amin = fminf(rmin[qq], o.y);
        float s = sRowBuf[rl];
        Mrow[qq] = fmaxf(fmaf(amax, CC, -s), fmaf(amin, -CC, s));
        rhi[qq] = (s + (Mrow[qq] - SKIP_T)) * INVCC;
        rlo[qq] = (s - (Mrow[qq] - SKIP_T)) * INVCC;
        Srow[qq] = 0.f;
    }

    // ---- row scan (rare path only does the real math) ----
    #pragma unroll
    for (int mf = 0; mf < 2; mf++)
        #pragma unroll
        for (int nf = 0; nf < 8; nf++)
            #pragma unroll
            for (int e = 0; e < 4; e++) {
                float a = acc[mf][nf][e];
                int qq = mf * 2 + (e >> 1);
                if (a > rhi[qq] || a < rlo[qq]) {
                    int rl = wr * 32 + (qq >> 1) * 16 + (qq & 1) * 8 + g;
                    float E = fabsf(fmaf(a, -CC, sRowBuf[rl]));
                    Srow[qq] += ex2f(E - Mrow[qq]);
                }
            }
    #pragma unroll
    for (int qq = 0; qq < 4; qq++) {
        Srow[qq] += __shfl_xor_sync(0xFFFFFFFFu, Srow[qq], 1);
        Srow[qq] += __shfl_xor_sync(0xFFFFFFFFu, Srow[qq], 2);
    }
    if (tig == 0) {
        #pragma unroll
        for (int qq = 0; qq < 4; qq++) {
            int rl = wr * 32 + (qq >> 1) * 16 + (qq & 1) * 8 + g;
            rowSbuf[wc * 128 + rl] = Srow[qq];
        }
    }
    __syncthreads();
    if (wc == 0 && tig == 0) {
        #pragma unroll
        for (int qq = 0; qq < 4; qq++) {
            int rl = wr * 32 + (qq >> 1) * 16 + (qq & 1) * 8 + g;
            float S = Srow[qq] + rowSbuf[128 + rl];
            g_c[(size_t)(row0 + rl) * NTILES + J] = make_float2(Mrow[qq], S);
        }
    }

    // ======== col direction ========
    if (!diag) {
        float chi[16], clo[16], Scol[16];
        #pragma unroll
        for (int ii = 0; ii < 16; ii++) {
            int cl = wc * 64 + (ii >> 1) * 8 + tig * 2 + (ii & 1);
            float2 th = gThr[cl];
            chi[ii] = th.x; clo[ii] = th.y; Scol[ii] = 0.f;
        }
        #pragma unroll
        for (int mf = 0; mf < 2; mf++)
            #pragma unroll
            for (int nf = 0; nf < 8; nf++)
                #pragma unroll
                for (int e = 0; e < 4; e++) {
                    float a = acc[mf][nf][e];
                    int ii = nf * 2 + (e & 1);
                    if (a > chi[ii] || a < clo[ii]) {
                        int cl = wc * 64 + nf * 8 + tig * 2 + (e & 1);
                        float E = fabsf(fmaf(a, -CC, sColBuf[cl]));
                        Scol[ii] += ex2f(E - gMcol[cl]);
                    }
                }
        #pragma unroll
        for (int ii = 0; ii < 16; ii++) {
            Scol[ii] += __shfl_xor_sync(0xFFFFFFFFu, Scol[ii], 4);
            Scol[ii] += __shfl_xor_sync(0xFFFFFFFFu, Scol[ii], 8);
            Scol[ii] += __shfl_xor_sync(0xFFFFFFFFu, Scol[ii], 16);
        }
        if (lane < 4) {
            #pragma unroll
            for (int ii = 0; ii < 16; ii++) {
                int cl = wc * 64 + (ii >> 1) * 8 + lane * 2 + (ii & 1);
                colSbuf[wr * 128 + cl] = Scol[ii];
            }
        }
        __syncthreads();
        if (wr == 0) {
            #pragma unroll
            for (int rep = 0; rep < 2; rep++) {
                int cl = wc * 64 + lane + rep * 32;
                float S = colSbuf[cl] + colSbuf[128 + cl] +
                          colSbuf[256 + cl] + colSbuf[384 + cl];
                g_c[(size_t)(col0 + cl) * NTILES + I] = make_float2(gMcol[cl], S);
            }
        }
    }
}

// ---------------- K3: warp-per-row combine of 64 contiguous partials --------
__global__ void k3_rows(int n, int ntiles) {
    int wid = threadIdx.x >> 5, lane = threadIdx.x & 31;
    int warpg = blockIdx.x * 8 + wid;
    float acc = 0.f;
    #pragma unroll
    for (int r = 0; r < 8; r++) {
        int row = warpg * 8 + r;
        float4 v = reinterpret_cast<const float4*>(g_c + (size_t)row * NTILES)[lane];
        float m = fmaxf(v.x, v.z);
        #pragma unroll
        for (int o = 16; o; o >>= 1) m = fmaxf(m, __shfl_xor_sync(0xFFFFFFFFu, m, o));
        float S = 0.f;
        if (v.x > m - 33.f) S += v.y * ex2f(v.x - m);
        if (v.z > m - 33.f) S += v.w * ex2f(v.z - m);
        #pragma unroll
        for (int o = 16; o; o >>= 1) S += __shfl_xor_sync(0xFFFFFFFFu, S, o);
        if (lane == 0) acc += (m + lg2f(S)) - g_dlabE[row];
    }
    __shared__ float red[8];
    if (lane == 0) red[wid] = acc;
    __syncthreads();
    if (threadIdx.x == 0) {
        float s = 0.f;
        #pragma unroll
        for (int k = 0; k < 8; k++) s += red[k];
        g_bpart[blockIdx.x] = s;
    }
}

// ---------------- K4: final reduce over 128 partials ----------------
__global__ void k4_final(float* __restrict__ out, int n) {
    __shared__ float red[128];
    int tid = threadIdx.x;
    red[tid] = g_bpart[tid];
    __syncthreads();
    #pragma unroll
    for (int s = 64; s > 0; s >>= 1) {
        if (tid < s) red[tid] += red[tid + s];
        __syncthreads();
    }
    if (tid == 0) out[0] = red[0] * (LN2F / (float)n);
}

// ---------------- launch ----------------
extern "C" void kernel_launch(void* const* d_in, const int* in_sizes, int n_in,
                              void* d_out, int out_size) {
    const float* q     = (const float*)d_in[0];
    const float* t     = (const float*)d_in[1];
    const int*   label = (const int*)d_in[2];
    const int*   jidx  = (const int*)d_in[3];
    int n = in_sizes[2];                     // 8192
    int ntiles = n / TM;                     // 64
    int pairs = ntiles * (ntiles + 1) / 2;   // 2080

    cudaFuncSetAttribute(k2_sym, cudaFuncAttributeMaxDynamicSharedMemorySize, SMEM_K2);

    k1_rowprep<<<n / 8, 256>>>(q, t, label, jidx, n);
    k2_sym<<<pairs, 256, SMEM_K2>>>(ntiles);
    k3_rows<<<n / 64, 256>>>(n, ntiles);     // 128 CTAs, warp-per-8-rows
    k4_final<<<1, 128>>>((float*)d_out, n);
}

// round 6
// speedup vs baseline: 1.0226x; 1.0226x over previous
#include <cuda_runtime.h>
#include <cuda_bf16.h>
#include <cstdint>

// ---------------- problem constants ----------------
#define NMAX    8192
#define DDIM    128
#define TM      128
#define NTILES  (NMAX / TM)           // 64
#define CC      14.426950408889634f   // log2(e) / TEMPERATURE(=0.1)
#define INVCC   0.069314718055994531f // 1/CC
#define LN2F    0.69314718055994531f
#define SKIP_T  25.0f

#define TILE_BYTES (TM * DDIM * 2)    // 32 KB bf16

// smem layout (bytes)
#define OFF_A      0
#define OFF_B      (TILE_BYTES)                 // 32768
#define OFF_SROW   (2 * TILE_BYTES)             // 128 f32
#define OFF_SCOL   (OFF_SROW + 512)             // 128 f32
#define OFF_ROWMM  (OFF_SCOL + 512)             // 2 x 128 float2 (max,min)
#define OFF_ROWS   (OFF_ROWMM + 2048)           // 2 x 128 f32
#define OFF_COLMM  (OFF_ROWS + 1024)            // 4 x 128 float2
#define OFF_THR    (OFF_COLMM + 4096)           // 128 float2 (cmid, chw)
#define OFF_MCOL   (OFF_THR + 1024)             // 128 f32
#define OFF_COLS   (OFF_MCOL + 512)             // 128 f32 (atomic sums)
#define SMEM_K2    (OFF_COLS + 512)             // 75776 B

__device__ __align__(16) __nv_bfloat16 g_tbf[NMAX * DDIM];
__device__ float  g_sC[NMAX];                    // s_i * CC
__device__ float  g_dlabE[NMAX];                 // |s_i - u_i| * CC
__device__ __align__(16) float2 g_c[NMAX * NTILES];  // [row][slot] = (max, sum)
__device__ float  g_sum;
__device__ int    g_count;

// ---------------- low-level helpers ----------------
__device__ __forceinline__ float ex2f(float x) {
    float r;
    asm("ex2.approx.f32 %0, %1;" : "=f"(r) : "f"(x));
    return r;
}
__device__ __forceinline__ float lg2f(float x) {
    float r;
    asm("lg2.approx.f32 %0, %1;" : "=f"(r) : "f"(x));
    return r;
}
__device__ __forceinline__ uint32_t smem_u32(const void* p) {
    uint32_t a;
    asm("{ .reg .u64 t; cvta.to.shared.u64 t, %1; cvt.u32.u64 %0, t; }" : "=r"(a) : "l"(p));
    return a;
}
__device__ __forceinline__ void cp_async16(uint32_t dst, const void* src) {
    asm volatile("cp.async.cg.shared.global [%0], [%1], 16;" :: "r"(dst), "l"(src) : "memory");
}
#define CP_COMMIT() asm volatile("cp.async.commit_group;" ::: "memory")
#define CP_WAIT0()  asm volatile("cp.async.wait_group 0;" ::: "memory")

#define LDSM_X4(r, addr)                                                      \
    asm volatile("ldmatrix.sync.aligned.m8n8.x4.shared.b16 {%0,%1,%2,%3}, [%4];" \
        : "=r"((r)[0]), "=r"((r)[1]), "=r"((r)[2]), "=r"((r)[3]) : "r"(addr))

__device__ __forceinline__ void mma16816(float* c, const uint32_t* a,
                                         uint32_t b0, uint32_t b1) {
    asm volatile(
        "mma.sync.aligned.m16n8k16.row.col.f32.bf16.bf16.f32 "
        "{%0,%1,%2,%3}, {%4,%5,%6,%7}, {%8,%9}, {%0,%1,%2,%3};"
        : "+f"(c[0]), "+f"(c[1]), "+f"(c[2]), "+f"(c[3])
        : "r"(a[0]), "r"(a[1]), "r"(a[2]), "r"(a[3]), "r"(b0), "r"(b1));
}
__device__ __forceinline__ uint32_t swz(int r, int c) {
    return (uint32_t)(r * 256 + ((c ^ (r & 7)) << 4));
}

// ---------------- K1: per-row scalars + t -> bf16 (fused) ----------------
__global__ void k1_rowprep(const float* __restrict__ q, const float* __restrict__ t,
                           const int* __restrict__ label, const int* __restrict__ jidx,
                           int n) {
    if (blockIdx.x == 0 && threadIdx.x == 0) { g_sum = 0.f; g_count = 0; }
    int i = blockIdx.x * 8 + (threadIdx.x >> 5);
    if (i >= n) return;
    int lane = threadIdx.x & 31;
    int j = jidx[i];

    float4 a = reinterpret_cast<const float4*>(q + (size_t)i * DDIM)[lane];
    float4 b = reinterpret_cast<const float4*>(q + (size_t)j * DDIM)[lane];
    float s = a.x * b.x + a.y * b.y + a.z * b.z + a.w * b.w;
    #pragma unroll
    for (int o = 16; o; o >>= 1) s += __shfl_xor_sync(0xFFFFFFFFu, s, o);

    int l = label[i];
    int col;
    if (l == i)       col = j;
    else if (j > i)   col = (l > i && l <= j) ? l - 1 : l;
    else              col = (l >= j && l < i) ? l + 1 : l;

    float4 c = reinterpret_cast<const float4*>(t + (size_t)i   * DDIM)[lane];
    float4 d = reinterpret_cast<const float4*>(t + (size_t)col * DDIM)[lane];
    float u = c.x * d.x + c.y * d.y + c.z * d.z + c.w * d.w;
    #pragma unroll
    for (int o = 16; o; o >>= 1) u += __shfl_xor_sync(0xFFFFFFFFu, u, o);

    __nv_bfloat162 p0, p1;
    p0.x = __float2bfloat16(c.x); p0.y = __float2bfloat16(c.y);
    p1.x = __float2bfloat16(c.z); p1.y = __float2bfloat16(c.w);
    uint2 pk;
    pk.x = *reinterpret_cast<uint32_t*>(&p0);
    pk.y = *reinterpret_cast<uint32_t*>(&p1);
    reinterpret_cast<uint2*>(g_tbf + (size_t)i * DDIM)[lane] = pk;

    if (lane == 0) {
        g_sC[i]    = s * CC;
        g_dlabE[i] = fabsf(s - u) * CC;
    }
}

// ---------------- K2: symmetric tiles + dual-direction LSE partials ----------
__global__ void __launch_bounds__(256, 2) k2_sym(int ntiles) {
    extern __shared__ char smem[];
    const int tid = threadIdx.x, wid = tid >> 5, lane = tid & 31;
    const int wr = wid & 3;
    const int wc = wid >> 2;
    const int g = lane >> 2, tig = lane & 3;

    // decode blockIdx -> (I, J), I <= J
    int b = blockIdx.x;
    int I;
    {
        float nn = 2.0f * ntiles + 1.0f;
        I = (int)((nn - sqrtf(nn * nn - 8.0f * (float)b)) * 0.5f);
        if (I < 0) I = 0;
        while ((I + 1) * ntiles - ((I + 1) * I) / 2 <= b) ++I;
        while (I * ntiles - (I * (I - 1)) / 2 > b) --I;
    }
    const int J = I + (b - (I * ntiles - (I * (I - 1)) / 2));
    const bool diag = (I == J);
    const int row0 = I * TM, col0 = J * TM;

    const uint32_t sA = smem_u32(smem);
    const uint32_t sB = diag ? sA : (sA + OFF_B);
    float*  sRowBuf = reinterpret_cast<float*>(smem + OFF_SROW);
    float*  sColBuf = reinterpret_cast<float*>(smem + OFF_SCOL);
    float2* rowMM   = reinterpret_cast<float2*>(smem + OFF_ROWMM);
    float*  rowSbuf = reinterpret_cast<float*>(smem + OFF_ROWS);
    float2* colMM   = reinterpret_cast<float2*>(smem + OFF_COLMM);
    float2* gThr    = reinterpret_cast<float2*>(smem + OFF_THR);
    float*  gMcol   = reinterpret_cast<float*>(smem + OFF_MCOL);
    float*  colS    = reinterpret_cast<float*>(smem + OFF_COLS);

    // ---- stage tiles + s vectors ----
    {
        const char* Ag = (const char*)(g_tbf + (size_t)row0 * DDIM);
        for (int idx = tid; idx < 2048; idx += 256)
            cp_async16(sA + swz(idx >> 4, idx & 15), Ag + idx * 16);
        if (!diag) {
            const char* Bg = (const char*)(g_tbf + (size_t)col0 * DDIM);
            for (int idx = tid; idx < 2048; idx += 256)
                cp_async16(sA + OFF_B + swz(idx >> 4, idx & 15), Bg + idx * 16);
        }
        if (tid < 128) sRowBuf[tid] = g_sC[row0 + tid];
        else           sColBuf[tid - 128] = g_sC[col0 + tid - 128];
        CP_COMMIT();
        CP_WAIT0();
        __syncthreads();
    }

    // ---- 128x128x128 MMA: warp does 32x64 ----
    float acc[2][8][4];
    #pragma unroll
    for (int mf = 0; mf < 2; mf++)
        #pragma unroll
        for (int nf = 0; nf < 8; nf++)
            #pragma unroll
            for (int e = 0; e < 4; e++) acc[mf][nf][e] = 0.f;

    #pragma unroll
    for (int kc = 0; kc < 8; kc++) {
        uint32_t a0[4], a1[4];
        {
            int r = wr * 32 + (lane & 15);
            int c = kc * 2 + (lane >> 4);
            LDSM_X4(a0, sA + swz(r, c));
            LDSM_X4(a1, sA + swz(r + 16, c));
        }
        #pragma unroll
        for (int p = 0; p < 4; p++) {
            uint32_t bb[4];
            int r = wc * 64 + p * 16 + ((lane >> 4) << 3) + (lane & 7);
            int c = kc * 2 + ((lane >> 3) & 1);
            LDSM_X4(bb, sB + swz(r, c));
            mma16816(acc[0][2 * p],     a0, bb[0], bb[1]);
            mma16816(acc[0][2 * p + 1], a0, bb[2], bb[3]);
            mma16816(acc[1][2 * p],     a1, bb[0], bb[1]);
            mma16816(acc[1][2 * p + 1], a1, bb[2], bb[3]);
        }
    }
    // frag coords: row_local = wr*32 + mf*16 + (e>>1)*8 + g
    //              col_local = wc*64 + nf*8 + tig*2 + (e&1)

    // ======== pass 1: raw max/min per row and per column ========
    float rmax[4], rmin[4];
    #pragma unroll
    for (int qq = 0; qq < 4; qq++) { rmax[qq] = -1e30f; rmin[qq] = 1e30f; }
    {
        float cmax[16], cmin[16];
        #pragma unroll
        for (int ii = 0; ii < 16; ii++) { cmax[ii] = -1e30f; cmin[ii] = 1e30f; }
        #pragma unroll
        for (int mf = 0; mf < 2; mf++)
            #pragma unroll
            for (int nf = 0; nf < 8; nf++)
                #pragma unroll
                for (int e = 0; e < 4; e++) {
                    float a = acc[mf][nf][e];
                    int qq = mf * 2 + (e >> 1), ii = nf * 2 + (e & 1);
                    rmax[qq] = fmaxf(rmax[qq], a);
                    rmin[qq] = fminf(rmin[qq], a);
                    cmax[ii] = fmaxf(cmax[ii], a);
                    cmin[ii] = fminf(cmin[ii], a);
                }
        // col merge across g (shfl 4,8,16); lanes 0-3 stage per warp-row
        if (!diag) {
            #pragma unroll
            for (int ii = 0; ii < 16; ii++) {
                cmax[ii] = fmaxf(cmax[ii], __shfl_xor_sync(0xFFFFFFFFu, cmax[ii], 4));
                cmax[ii] = fmaxf(cmax[ii], __shfl_xor_sync(0xFFFFFFFFu, cmax[ii], 8));
                cmax[ii] = fmaxf(cmax[ii], __shfl_xor_sync(0xFFFFFFFFu, cmax[ii], 16));
                cmin[ii] = fminf(cmin[ii], __shfl_xor_sync(0xFFFFFFFFu, cmin[ii], 4));
                cmin[ii] = fminf(cmin[ii], __shfl_xor_sync(0xFFFFFFFFu, cmin[ii], 8));
                cmin[ii] = fminf(cmin[ii], __shfl_xor_sync(0xFFFFFFFFu, cmin[ii], 16));
            }
            if (lane < 4) {
                #pragma unroll
                for (int ii = 0; ii < 16; ii++) {
                    int cl = wc * 64 + (ii >> 1) * 8 + lane * 2 + (ii & 1);
                    colMM[wr * 128 + cl] = make_float2(cmax[ii], cmin[ii]);
                }
            }
        }
    }
    // row merge across tig
    #pragma unroll
    for (int qq = 0; qq < 4; qq++) {
        rmax[qq] = fmaxf(rmax[qq], __shfl_xor_sync(0xFFFFFFFFu, rmax[qq], 1));
        rmax[qq] = fmaxf(rmax[qq], __shfl_xor_sync(0xFFFFFFFFu, rmax[qq], 2));
        rmin[qq] = fminf(rmin[qq], __shfl_xor_sync(0xFFFFFFFFu, rmin[qq], 1));
        rmin[qq] = fminf(rmin[qq], __shfl_xor_sync(0xFFFFFFFFu, rmin[qq], 2));
    }
    if (tig == 0) {
        #pragma unroll
        for (int qq = 0; qq < 4; qq++) {
            int rl = wr * 32 + (qq >> 1) * 16 + (qq & 1) * 8 + g;
            rowMM[wc * 128 + rl] = make_float2(rmax[qq], rmin[qq]);
        }
    }
    if (tid < 128) colS[tid] = 0.f;    // zero atomic sums (covered by barrier below)
    __syncthreads();

    // ---- per-column thresholds (wid 0 & 4 compute 64 cols each) ----
    if (!diag && wr == 0) {
        #pragma unroll
        for (int rep = 0; rep < 2; rep++) {
            int cl = wc * 64 + lane + rep * 32;
            float2 v0 = colMM[cl], v1 = colMM[128 + cl];
            float2 v2 = colMM[256 + cl], v3 = colMM[384 + cl];
            float m = fmaxf(fmaxf(v0.x, v1.x), fmaxf(v2.x, v3.x));
            float mn = fminf(fminf(v0.y, v1.y), fminf(v2.y, v3.y));
            float sc = sColBuf[cl];
            float Mc = fmaxf(fmaf(m, CC, -sc), fmaf(mn, -CC, sc));
            gMcol[cl] = Mc;
            gThr[cl] = make_float2(sc * INVCC, (Mc - SKIP_T) * INVCC);
        }
    }
    __syncthreads();

    // ---- row thresholds (regs) ----
    float Mrow[4], rmid[4], rhw[4], Srow[4];
    #pragma unroll
    for (int qq = 0; qq < 4; qq++) {
        int rl = wr * 32 + (qq >> 1) * 16 + (qq & 1) * 8 + g;
        float2 o = rowMM[(1 - wc) * 128 + rl];
        float amax = fmaxf(rmax[qq], o.x);
        float amin = fminf(rmin[qq], o.y);
        float s = sRowBuf[rl];
        Mrow[qq] = fmaxf(fmaf(amax, CC, -s), fmaf(amin, -CC, s));
        rmid[qq] = s * INVCC;
        rhw[qq]  = (Mrow[qq] - SKIP_T) * INVCC;
        Srow[qq] = 0.f;
    }

    // ======== fused scan: both directions, rare-path-only math ========
    if (diag) {
        #pragma unroll
        for (int mf = 0; mf < 2; mf++)
            #pragma unroll
            for (int nf = 0; nf < 8; nf++)
                #pragma unroll
                for (int e = 0; e < 4; e++) {
                    float a = acc[mf][nf][e];
                    int qq = mf * 2 + (e >> 1);
                    float dr = a - rmid[qq];
                    if (fabsf(dr) > rhw[qq])
                        Srow[qq] += ex2f(fmaf(fabsf(dr), CC, -Mrow[qq]));
                }
    } else {
        #pragma unroll
        for (int mf = 0; mf < 2; mf++)
            #pragma unroll
            for (int nf = 0; nf < 8; nf++) {
                int cl0 = wc * 64 + nf * 8 + tig * 2;
                float2 t0 = gThr[cl0], t1 = gThr[cl0 + 1];
                #pragma unroll
                for (int e = 0; e < 4; e++) {
                    float a = acc[mf][nf][e];
                    int qq = mf * 2 + (e >> 1);
                    float dr = a - rmid[qq];
                    if (fabsf(dr) > rhw[qq])
                        Srow[qq] += ex2f(fmaf(fabsf(dr), CC, -Mrow[qq]));
                    float2 tc = (e & 1) ? t1 : t0;
                    float dc = a - tc.x;
                    if (fabsf(dc) > tc.y) {
                        int cl = cl0 + (e & 1);
                        atomicAdd(&colS[cl], ex2f(fmaf(fabsf(dc), CC, -gMcol[cl])));
                    }
                }
            }
    }

    // ---- row sum merge + write ----
    #pragma unroll
    for (int qq = 0; qq < 4; qq++) {
        Srow[qq] += __shfl_xor_sync(0xFFFFFFFFu, Srow[qq], 1);
        Srow[qq] += __shfl_xor_sync(0xFFFFFFFFu, Srow[qq], 2);
    }
    if (tig == 0) {
        #pragma unroll
        for (int qq = 0; qq < 4; qq++) {
            int rl = wr * 32 + (qq >> 1) * 16 + (qq & 1) * 8 + g;
            rowSbuf[wc * 128 + rl] = Srow[qq];
        }
    }
    __syncthreads();
    if (wc == 0 && tig == 0) {
        #pragma unroll
        for (int qq = 0; qq < 4; qq++) {
            int rl = wr * 32 + (qq >> 1) * 16 + (qq & 1) * 8 + g;
            float S = Srow[qq] + rowSbuf[128 + rl];
            g_c[(size_t)(row0 + rl) * NTILES + J] = make_float2(Mrow[qq], S);
        }
    }
    // ---- col write (atomic sums are complete after the barrier) ----
    if (!diag && wr == 0) {
        #pragma unroll
        for (int rep = 0; rep < 2; rep++) {
            int cl = wc * 64 + lane + rep * 32;
            g_c[(size_t)(col0 + cl) * NTILES + I] = make_float2(gMcol[cl], colS[cl]);
        }
    }
}

// ---------------- K3: combine per-row partials + global finisher ----------
__global__ void k3_rows(float* __restrict__ out, int n, int ntiles) {
    int wid = threadIdx.x >> 5, lane = threadIdx.x & 31;
    int warpg = blockIdx.x * 8 + wid;
    float acc = 0.f;
    #pragma unroll
    for (int r = 0; r < 8; r++) {
        int row = warpg * 8 + r;
        float4 v = reinterpret_cast<const float4*>(g_c + (size_t)row * NTILES)[lane];
        float m = fmaxf(v.x, v.z);
        #pragma unroll
        for (int o = 16; o; o >>= 1) m = fmaxf(m, __shfl_xor_sync(0xFFFFFFFFu, m, o));
        float S = 0.f;
        if (v.x > m - 33.f) S += v.y * ex2f(v.x - m);
        if (v.z > m - 33.f) S += v.w * ex2f(v.z - m);
        #pragma unroll
        for (int o = 16; o; o >>= 1) S += __shfl_xor_sync(0xFFFFFFFFu, S, o);
        if (lane == 0) acc += (m + lg2f(S)) - g_dlabE[row];
    }
    __shared__ float red[8];
    if (lane == 0) red[wid] = acc;
    __syncthreads();
    if (threadIdx.x == 0) {
        float s = 0.f;
        #pragma unroll
        for (int k = 0; k < 8; k++) s += red[k];
        atomicAdd(&g_sum, s);
        __threadfence();
        int c = atomicAdd(&g_count, 1);
        if (c == (int)gridDim.x - 1)
            out[0] = g_sum * (LN2F / (float)n);
    }
}

// ---------------- launch ----------------
extern "C" void kernel_launch(void* const* d_in, const int* in_sizes, int n_in,
                              void* d_out, int out_size) {
    const float* q     = (const float*)d_in[0];
    const float* t     = (const float*)d_in[1];
    const int*   label = (const int*)d_in[2];
    const int*   jidx  = (const int*)d_in[3];
    int n = in_sizes[2];                     // 8192
    int ntiles = n / TM;                     // 64
    int pairs = ntiles * (ntiles + 1) / 2;   // 2080

    cudaFuncSetAttribute(k2_sym, cudaFuncAttributeMaxDynamicSharedMemorySize, SMEM_K2);

    k1_rowprep<<<n / 8, 256>>>(q, t, label, jidx, n);
    k2_sym<<<pairs, 256, SMEM_K2>>>(ntiles);
    k3_rows<<<n / 64, 256>>>((float*)d_out, n, ntiles);
}

// round 7
// speedup vs baseline: 1.0269x; 1.0042x over previous
#include <cuda_runtime.h>
#include <cuda_bf16.h>
#include <cstdint>

// ---------------- problem constants ----------------
#define NMAX    8192
#define DDIM    128
#define TM      128
#define NTILES  (NMAX / TM)           // 64
#define CC      14.426950408889634f   // log2(e) / TEMPERATURE(=0.1)
#define INVCC   0.069314718055994531f // 1/CC
#define LN2F    0.69314718055994531f
#define SKIP_T  25.0f
#define NCTA    296                   // 148 SMs x 2

#define TILE_BYTES (TM * DDIM * 2)    // 32 KB bf16

// smem layout (bytes)
#define OFF_A      0
#define OFF_B0     32768
#define OFF_B1     65536
#define OFF_SROW   98304              // 2 x 512 (double-buffered)
#define OFF_SCOL   99328              // 2 x 512
#define OFF_ROWMM  100352             // 2 x 128 float2
#define OFF_ROWS   102400             // 2 x 128 f32
#define OFF_COLMM  103424             // 4 x 128 float2
#define OFF_THR    107520             // 128 float2
#define OFF_MCOL   108544             // 128 f32
#define OFF_COLS   109056             // 128 f32 (atomic sums)
#define SMEM_K2    109568

__device__ __align__(16) __nv_bfloat16 g_tbf[NMAX * DDIM];
__device__ __align__(16) float g_sC[NMAX];       // s_i * CC
__device__ float  g_dlabE[NMAX];                 // |s_i - u_i| * CC
__device__ __align__(16) float2 g_c[NMAX * NTILES];  // [row][slot]
__device__ float  g_sum;
__device__ int    g_count;

// ---------------- low-level helpers ----------------
__device__ __forceinline__ float ex2f(float x) {
    float r;
    asm("ex2.approx.f32 %0, %1;" : "=f"(r) : "f"(x));
    return r;
}
__device__ __forceinline__ float lg2f(float x) {
    float r;
    asm("lg2.approx.f32 %0, %1;" : "=f"(r) : "f"(x));
    return r;
}
__device__ __forceinline__ uint32_t smem_u32(const void* p) {
    uint32_t a;
    asm("{ .reg .u64 t; cvta.to.shared.u64 t, %1; cvt.u32.u64 %0, t; }" : "=r"(a) : "l"(p));
    return a;
}
__device__ __forceinline__ void cp_async16(uint32_t dst, const void* src) {
    asm volatile("cp.async.cg.shared.global [%0], [%1], 16;" :: "r"(dst), "l"(src) : "memory");
}
#define CP_COMMIT() asm volatile("cp.async.commit_group;" ::: "memory")
#define CP_WAIT0()  asm volatile("cp.async.wait_group 0;" ::: "memory")

#define LDSM_X4(r, addr)                                                      \
    asm volatile("ldmatrix.sync.aligned.m8n8.x4.shared.b16 {%0,%1,%2,%3}, [%4];" \
        : "=r"((r)[0]), "=r"((r)[1]), "=r"((r)[2]), "=r"((r)[3]) : "r"(addr))

__device__ __forceinline__ void mma16816(float* c, const uint32_t* a,
                                         uint32_t b0, uint32_t b1) {
    asm volatile(
        "mma.sync.aligned.m16n8k16.row.col.f32.bf16.bf16.f32 "
        "{%0,%1,%2,%3}, {%4,%5,%6,%7}, {%8,%9}, {%0,%1,%2,%3};"
        : "+f"(c[0]), "+f"(c[1]), "+f"(c[2]), "+f"(c[3])
        : "r"(a[0]), "r"(a[1]), "r"(a[2]), "r"(a[3]), "r"(b0), "r"(b1));
}
__device__ __forceinline__ uint32_t swz(int r, int c) {
    return (uint32_t)(r * 256 + ((c ^ (r & 7)) << 4));
}

// ---------------- K1: per-row scalars + t -> bf16 (fused) ----------------
__global__ void k1_rowprep(const float* __restrict__ q, const float* __restrict__ t,
                           const int* __restrict__ label, const int* __restrict__ jidx,
                           int n) {
    if (blockIdx.x == 0 && threadIdx.x == 0) { g_sum = 0.f; g_count = 0; }
    int i = blockIdx.x * 8 + (threadIdx.x >> 5);
    if (i >= n) return;
    int lane = threadIdx.x & 31;
    int j = jidx[i];

    float4 a = reinterpret_cast<const float4*>(q + (size_t)i * DDIM)[lane];
    float4 b = reinterpret_cast<const float4*>(q + (size_t)j * DDIM)[lane];
    float s = a.x * b.x + a.y * b.y + a.z * b.z + a.w * b.w;
    #pragma unroll
    for (int o = 16; o; o >>= 1) s += __shfl_xor_sync(0xFFFFFFFFu, s, o);

    int l = label[i];
    int col;
    if (l == i)       col = j;
    else if (j > i)   col = (l > i && l <= j) ? l - 1 : l;
    else              col = (l >= j && l < i) ? l + 1 : l;

    float4 c = reinterpret_cast<const float4*>(t + (size_t)i   * DDIM)[lane];
    float4 d = reinterpret_cast<const float4*>(t + (size_t)col * DDIM)[lane];
    float u = c.x * d.x + c.y * d.y + c.z * d.z + c.w * d.w;
    #pragma unroll
    for (int o = 16; o; o >>= 1) u += __shfl_xor_sync(0xFFFFFFFFu, u, o);

    __nv_bfloat162 p0, p1;
    p0.x = __float2bfloat16(c.x); p0.y = __float2bfloat16(c.y);
    p1.x = __float2bfloat16(c.z); p1.y = __float2bfloat16(c.w);
    uint2 pk;
    pk.x = *reinterpret_cast<uint32_t*>(&p0);
    pk.y = *reinterpret_cast<uint32_t*>(&p1);
    reinterpret_cast<uint2*>(g_tbf + (size_t)i * DDIM)[lane] = pk;

    if (lane == 0) {
        g_sC[i]    = s * CC;
        g_dlabE[i] = fabsf(s - u) * CC;
    }
}

// ---------------- K2: persistent pipelined symmetric tiles ----------------
__global__ void __launch_bounds__(256, 2) k2_sym(int ntiles) {
    extern __shared__ char smem[];
    const int tid = threadIdx.x, wid = tid >> 5, lane = tid & 31;
    const int wr = wid & 3;
    const int wc = wid >> 2;
    const int g = lane >> 2, tig = lane & 3;

    const uint32_t sA = smem_u32(smem);
    float*  sRowB  = reinterpret_cast<float*>(smem + OFF_SROW);
    float*  sColB  = reinterpret_cast<float*>(smem + OFF_SCOL);
    float2* rowMM  = reinterpret_cast<float2*>(smem + OFF_ROWMM);
    float*  rowSbuf= reinterpret_cast<float*>(smem + OFF_ROWS);
    float2* colMM  = reinterpret_cast<float2*>(smem + OFF_COLMM);
    float2* gThr   = reinterpret_cast<float2*>(smem + OFF_THR);
    float*  gMcol  = reinterpret_cast<float*>(smem + OFF_MCOL);
    float*  colS   = reinterpret_cast<float*>(smem + OFF_COLS);

    // ---- my chunk of pairs (row-major over I<=J) ----
    const int k = blockIdx.x;
    const int base = k * 7 + (k < 8 ? k : 8);
    const int cnt  = 7 + (k < 8 ? 1 : 0);

    int I = 0;
    while ((I + 1) * ntiles - ((I + 1) * I) / 2 <= base) ++I;
    int J = I + (base - (I * ntiles - (I * (I - 1)) / 2));

    // ---- prologue: load A(I), B0(J), s vectors (buffer 0) ----
    {
        const char* Ag = (const char*)(g_tbf + (size_t)I * TM * DDIM);
        const char* Bg = (const char*)(g_tbf + (size_t)J * TM * DDIM);
        for (int idx = tid; idx < 2048; idx += 256) {
            cp_async16(sA + swz(idx >> 4, idx & 15), Ag + idx * 16);
            cp_async16(sA + OFF_B0 + swz(idx >> 4, idx & 15), Bg + idx * 16);
        }
        if (tid < 32)            cp_async16(sA + OFF_SROW + tid * 16, g_sC + I * TM + (tid & 31) * 4);
        else if (tid < 64)       cp_async16(sA + OFF_SCOL + (tid & 31) * 16, g_sC + J * TM + (tid & 31) * 4);
        CP_COMMIT();
        CP_WAIT0();
        __syncthreads();
    }

    for (int idx = 0; idx < cnt; ++idx) {
        const int cur = idx & 1;
        const uint32_t sB = sA + (cur ? OFF_B1 : OFF_B0);
        const bool diag = (I == J);
        const int row0 = I * TM, col0 = J * TM;
        const float* sRowBuf = sRowB + cur * 128;
        const float* sColBuf = sColB + cur * 128;
        const bool hasNext = (idx + 1 < cnt);
        int In = I, Jn = J + 1;
        if (Jn >= ntiles) { In = I + 1; Jn = In; }

        // ---- 128x128x128 MMA: warp does 32x64 ----
        float acc[2][8][4];
        #pragma unroll
        for (int mf = 0; mf < 2; mf++)
            #pragma unroll
            for (int nf = 0; nf < 8; nf++)
                #pragma unroll
                for (int e = 0; e < 4; e++) acc[mf][nf][e] = 0.f;

        #pragma unroll
        for (int kc = 0; kc < 8; kc++) {
            uint32_t a0[4], a1[4];
            {
                int r = wr * 32 + (lane & 15);
                int c = kc * 2 + (lane >> 4);
                LDSM_X4(a0, sA + swz(r, c));
                LDSM_X4(a1, sA + swz(r + 16, c));
            }
            #pragma unroll
            for (int p = 0; p < 4; p++) {
                uint32_t bb[4];
                int r = wc * 64 + p * 16 + ((lane >> 4) << 3) + (lane & 7);
                int c = kc * 2 + ((lane >> 3) & 1);
                LDSM_X4(bb, sB + swz(r, c));
                mma16816(acc[0][2 * p],     a0, bb[0], bb[1]);
                mma16816(acc[0][2 * p + 1], a0, bb[2], bb[3]);
                mma16816(acc[1][2 * p],     a1, bb[0], bb[1]);
                mma16816(acc[1][2 * p + 1], a1, bb[2], bb[3]);
            }
        }
        // frag coords: row_local = wr*32 + mf*16 + (e>>1)*8 + g
        //              col_local = wc*64 + nf*8 + tig*2 + (e&1)

        // ======== pass 1: raw max/min per row and per column ========
        float rmax[4], rmin[4];
        #pragma unroll
        for (int qq = 0; qq < 4; qq++) { rmax[qq] = -1e30f; rmin[qq] = 1e30f; }
        {
            float cmax[16], cmin[16];
            #pragma unroll
            for (int ii = 0; ii < 16; ii++) { cmax[ii] = -1e30f; cmin[ii] = 1e30f; }
            #pragma unroll
            for (int mf = 0; mf < 2; mf++)
                #pragma unroll
                for (int nf = 0; nf < 8; nf++)
                    #pragma unroll
                    for (int e = 0; e < 4; e++) {
                        float a = acc[mf][nf][e];
                        int qq = mf * 2 + (e >> 1), ii = nf * 2 + (e & 1);
                        rmax[qq] = fmaxf(rmax[qq], a);
                        rmin[qq] = fminf(rmin[qq], a);
                        cmax[ii] = fmaxf(cmax[ii], a);
                        cmin[ii] = fminf(cmin[ii], a);
                    }
            if (!diag) {
                #pragma unroll
                for (int ii = 0; ii < 16; ii++) {
                    cmax[ii] = fmaxf(cmax[ii], __shfl_xor_sync(0xFFFFFFFFu, cmax[ii], 4));
                    cmax[ii] = fmaxf(cmax[ii], __shfl_xor_sync(0xFFFFFFFFu, cmax[ii], 8));
                    cmax[ii] = fmaxf(cmax[ii], __shfl_xor_sync(0xFFFFFFFFu, cmax[ii], 16));
                    cmin[ii] = fminf(cmin[ii], __shfl_xor_sync(0xFFFFFFFFu, cmin[ii], 4));
                    cmin[ii] = fminf(cmin[ii], __shfl_xor_sync(0xFFFFFFFFu, cmin[ii], 8));
                    cmin[ii] = fminf(cmin[ii], __shfl_xor_sync(0xFFFFFFFFu, cmin[ii], 16));
                }
                if (lane < 4) {
                    #pragma unroll
                    for (int ii = 0; ii < 16; ii++) {
                        int cl = wc * 64 + (ii >> 1) * 8 + lane * 2 + (ii & 1);
                        colMM[wr * 128 + cl] = make_float2(cmax[ii], cmin[ii]);
                    }
                }
            }
        }
        #pragma unroll
        for (int qq = 0; qq < 4; qq++) {
            rmax[qq] = fmaxf(rmax[qq], __shfl_xor_sync(0xFFFFFFFFu, rmax[qq], 1));
            rmax[qq] = fmaxf(rmax[qq], __shfl_xor_sync(0xFFFFFFFFu, rmax[qq], 2));
            rmin[qq] = fminf(rmin[qq], __shfl_xor_sync(0xFFFFFFFFu, rmin[qq], 1));
            rmin[qq] = fminf(rmin[qq], __shfl_xor_sync(0xFFFFFFFFu, rmin[qq], 2));
        }
        if (tig == 0) {
            #pragma unroll
            for (int qq = 0; qq < 4; qq++) {
                int rl = wr * 32 + (qq >> 1) * 16 + (qq & 1) * 8 + g;
                rowMM[wc * 128 + rl] = make_float2(rmax[qq], rmin[qq]);
            }
        }
        if (tid < 128) colS[tid] = 0.f;
        __syncthreads();                              // barrier #1 (MMA reads done)

        // ---- prefetch next pair (overlaps rest of epilogue) ----
        if (hasNext) {
            const int nb = 1 - cur;
            const char* Bg = (const char*)(g_tbf + (size_t)Jn * TM * DDIM);
            const uint32_t dB = sA + (nb ? OFF_B1 : OFF_B0);
            for (int ix = tid; ix < 2048; ix += 256)
                cp_async16(dB + swz(ix >> 4, ix & 15), Bg + ix * 16);
            if (tid < 32)      cp_async16(sA + OFF_SCOL + nb * 512 + tid * 16, g_sC + Jn * TM + tid * 4);
            else if (tid < 64) cp_async16(sA + OFF_SROW + nb * 512 + (tid & 31) * 16, g_sC + In * TM + (tid & 31) * 4);
            if (In != I) {
                const char* Ag = (const char*)(g_tbf + (size_t)In * TM * DDIM);
                for (int ix = tid; ix < 2048; ix += 256)
                    cp_async16(sA + swz(ix >> 4, ix & 15), Ag + ix * 16);
            }
            CP_COMMIT();
        }

        // ---- per-column thresholds ----
        if (!diag && wr == 0) {
            #pragma unroll
            for (int rep = 0; rep < 2; rep++) {
                int cl = wc * 64 + lane + rep * 32;
                float2 v0 = colMM[cl], v1 = colMM[128 + cl];
                float2 v2 = colMM[256 + cl], v3 = colMM[384 + cl];
                float m  = fmaxf(fmaxf(v0.x, v1.x), fmaxf(v2.x, v3.x));
                float mn = fminf(fminf(v0.y, v1.y), fminf(v2.y, v3.y));
                float sc = sColBuf[cl];
                float Mc = fmaxf(fmaf(m, CC, -sc), fmaf(mn, -CC, sc));
                gMcol[cl] = Mc;
                gThr[cl] = make_float2(sc * INVCC, (Mc - SKIP_T) * INVCC);
            }
        }
        __syncthreads();                              // barrier #2

        // ---- row thresholds ----
        float Mrow[4], rmid[4], rhw[4], Srow[4];
        #pragma unroll
        for (int qq = 0; qq < 4; qq++) {
            int rl = wr * 32 + (qq >> 1) * 16 + (qq & 1) * 8 + g;
            float2 o = rowMM[(1 - wc) * 128 + rl];
            float amax = fmaxf(rmax[qq], o.x);
            float amin = fminf(rmin[qq], o.y);
            float s = sRowBuf[rl];
            Mrow[qq] = fmaxf(fmaf(amax, CC, -s), fmaf(amin, -CC, s));
            rmid[qq] = s * INVCC;
            rhw[qq]  = (Mrow[qq] - SKIP_T) * INVCC;
            Srow[qq] = 0.f;
        }

        // ======== fused scan (rare-path-only math) ========
        if (diag) {
            #pragma unroll
            for (int mf = 0; mf < 2; mf++)
                #pragma unroll
                for (int nf = 0; nf < 8; nf++)
                    #pragma unroll
                    for (int e = 0; e < 4; e++) {
                        float a = acc[mf][nf][e];
                        int qq = mf * 2 + (e >> 1);
                        float dr = a - rmid[qq];
                        if (fabsf(dr) > rhw[qq])
                            Srow[qq] += ex2f(fmaf(fabsf(dr), CC, -Mrow[qq]));
                    }
        } else {
            #pragma unroll
            for (int mf = 0; mf < 2; mf++)
                #pragma unroll
                for (int nf = 0; nf < 8; nf++) {
                    int cl0 = wc * 64 + nf * 8 + tig * 2;
                    float2 t0 = gThr[cl0], t1 = gThr[cl0 + 1];
                    #pragma unroll
                    for (int e = 0; e < 4; e++) {
                        float a = acc[mf][nf][e];
                        int qq = mf * 2 + (e >> 1);
                        float dr = a - rmid[qq];
                        if (fabsf(dr) > rhw[qq])
                            Srow[qq] += ex2f(fmaf(fabsf(dr), CC, -Mrow[qq]));
                        float2 tc = (e & 1) ? t1 : t0;
                        float dc = a - tc.x;
                        if (fabsf(dc) > tc.y) {
                            int cl = cl0 + (e & 1);
                            atomicAdd(&colS[cl], ex2f(fmaf(fabsf(dc), CC, -gMcol[cl])));
                        }
                    }
                }
        }

        // ---- row sum merge + write ----
        #pragma unroll
        for (int qq = 0; qq < 4; qq++) {
            Srow[qq] += __shfl_xor_sync(0xFFFFFFFFu, Srow[qq], 1);
            Srow[qq] += __shfl_xor_sync(0xFFFFFFFFu, Srow[qq], 2);
        }
        if (tig == 0) {
            #pragma unroll
            for (int qq = 0; qq < 4; qq++) {
                int rl = wr * 32 + (qq >> 1) * 16 + (qq & 1) * 8 + g;
                rowSbuf[wc * 128 + rl] = Srow[qq];
            }
        }
        __syncthreads();                              // barrier #3
        if (wc == 0 && tig == 0) {
            #pragma unroll
            for (int qq = 0; qq < 4; qq++) {
                int rl = wr * 32 + (qq >> 1) * 16 + (qq & 1) * 8 + g;
                float S = Srow[qq] + rowSbuf[128 + rl];
                g_c[(size_t)(row0 + rl) * NTILES + J] = make_float2(Mrow[qq], S);
            }
        }
        if (!diag && wr == 0) {
            #pragma unroll
            for (int rep = 0; rep < 2; rep++) {
                int cl = wc * 64 + lane + rep * 32;
                g_c[(size_t)(col0 + cl) * NTILES + I] = make_float2(gMcol[cl], colS[cl]);
            }
        }

        I = In; J = Jn;
        CP_WAIT0();
        __syncthreads();                              // next buffers ready
    }
}

// ---------------- K3: combine per-row partials + global finisher ----------
__global__ void k3_rows(float* __restrict__ out, int n, int ntiles) {
    int wid = threadIdx.x >> 5, lane = threadIdx.x & 31;
    int warpg = blockIdx.x * 8 + wid;
    float acc = 0.f;
    #pragma unroll
    for (int r = 0; r < 8; r++) {
        int row = warpg * 8 + r;
        float4 v = reinterpret_cast<const float4*>(g_c + (size_t)row * NTILES)[lane];
        float m = fmaxf(v.x, v.z);
        #pragma unroll
        for (int o = 16; o; o >>= 1) m = fmaxf(m, __shfl_xor_sync(0xFFFFFFFFu, m, o));
        float S = 0.f;
        if (v.x > m - 33.f) S += v.y * ex2f(v.x - m);
        if (v.z > m - 33.f) S += v.w * ex2f(v.z - m);
        #pragma unroll
        for (int o = 16; o; o >>= 1) S += __shfl_xor_sync(0xFFFFFFFFu, S, o);
        if (lane == 0) acc += (m + lg2f(S)) - g_dlabE[row];
    }
    __shared__ float red[8];
    if (lane == 0) red[wid] = acc;
    __syncthreads();
    if (threadIdx.x == 0) {
        float s = 0.f;
        #pragma unroll
        for (int kk = 0; kk < 8; kk++) s += red[kk];
        atomicAdd(&g_sum, s);
        __threadfence();
        int c = atomicAdd(&g_count, 1);
        if (c == (int)gridDim.x - 1)
            out[0] = g_sum * (LN2F / (float)n);
    }
}

// ---------------- launch ----------------
extern "C" void kernel_launch(void* const* d_in, const int* in_sizes, int n_in,
                              void* d_out, int out_size) {
    const float* q     = (const float*)d_in[0];
    const float* t     = (const float*)d_in[1];
    const int*   label = (const int*)d_in[2];
    const int*   jidx  = (const int*)d_in[3];
    int n = in_sizes[2];                     // 8192
    int ntiles = n / TM;                     // 64

    cudaFuncSetAttribute(k2_sym, cudaFuncAttributeMaxDynamicSharedMemorySize, SMEM_K2);

    k1_rowprep<<<n / 8, 256>>>(q, t, label, jidx, n);
    k2_sym<<<NCTA, 256, SMEM_K2>>>(ntiles);
    k3_rows<<<n / 64, 256>>>((float*)d_out, n, ntiles);
}